// round 14
// baseline (speedup 1.0000x reference)
#include <cuda_runtime.h>

// Problem constants (fixed by setup_inputs)
#define B_    4
#define C_    256
#define H_    256
#define W_    512
#define FS    14
#define NP    (FS*FS)        // 196
#define NROI  400            // B * MAXLOAD
#define HW    (H_*W_)        // 131072
#define HB    (B_*H_)        // 1024 stacked rows
#define KCH   4              // channels per thread
#define OCT   8              // channels per warp (2 lane-groups x KCH)
#define NOCT  (C_/OCT)       // 32 channel octets

#define THREADS 256
#define WPB     (THREADS/32) // 8 warps per block

#define OUT_MAIN_I  20070400                       // NROI*C_*NP
#define MAIN_WARPS  (NOCT * NROI * FS)             // 179,200
#define MAIN_BLOCKS (MAIN_WARPS / WPB)             // 22,400 (exact)

__global__ __launch_bounds__(THREADS)
void pooler_rowwarp_kernel(const float* __restrict__ feat,
                           const float* __restrict__ rois,
                           float*       __restrict__ out,
                           int out_size)
{
    const int blk  = blockIdx.x;
    const int tid  = threadIdx.x;
    const int lane = tid & 31;

    // Tail: val_bind = repeat(arange(B), MAXLOAD) appended after main output.
    if (blk >= MAIN_BLOCKS) {
        int k   = (blk - MAIN_BLOCKS) * THREADS + tid;
        int idx = OUT_MAIN_I + k;
        if (idx < out_size) out[idx] = (float)(k / 100);
        return;
    }
    if (lane >= 28) return;                  // 28 active lanes per warp

    // warp -> (oct slow, n mid, i fast): slab ordering preserved.
    int gw   = blk * WPB + (tid >> 5);
    int i    = gw % FS;
    int rest = gw / FS;
    int n    = rest % NROI;
    int oct  = rest / NROI;

    // lane -> (cl, j): one grid-row i per warp, 2 channel-groups x 14 samples.
    int cl = lane >= FS;
    int j  = lane - (cl ? FS : 0);
    int c  = oct * OCT + cl * KCH;
    int b  = n / 100;                        // roi's batch

    const float4 r = reinterpret_cast<const float4*>(rois)[n];
    const float inv13 = 1.0f / 13.0f;

    float scalex = r.z - r.x;
    float scaley = r.w - r.y;
    float biasy  = r.y + (float)b * 1024.0f; // image_height

    float gridx = ((float)j * inv13 * scalex + r.x)  * 0.25f;  // /shrink_scale
    float gridy = ((float)i * inv13 * scaley + biasy) * 0.25f;

    // normalized-grid round trip, exactly as reference
    float gx = (gridx * (1.0f / (W_ - 1)) - 0.5f) * 2.0f;
    float gy = (gridy * (1.0f / (HB - 1)) - 0.5f) * 2.0f;
    float px = ((gx + 1.0f) * (float)W_ - 1.0f) * 0.5f;
    float py = ((gy + 1.0f) * (float)HB - 1.0f) * 0.5f;
    px = fminf(fmaxf(px, 0.0f), (float)(W_ - 1));
    py = fminf(fmaxf(py, 0.0f), (float)(HB - 1));

    float x0f = floorf(px);
    float y0f = floorf(py);
    float wx  = px - x0f;
    float wy  = py - y0f;
    int x0 = (int)x0f;
    int y0 = (int)y0f;
    int x1 = min(x0 + 1, W_ - 1);
    int y1 = min(y0 + 1, HB - 1);

    // feats view (C, B*H, W); element indices fit in int32 (max ~134M)
    int a0 = ((y0 >> 8) * C_ + c) * HW + (y0 & 255) * W_;
    int a1 = ((y1 >> 8) * C_ + c) * HW + (y1 & 255) * W_;

    // Front-batched independent loads (16 LDG.32). Each warp-instruction now
    // touches exactly 2 channel-rows (cl=0/1), one grid-row -> ~8-9 L1 lines
    // instead of ~13 with the 3-row-straddling layout.
    float f00[KCH], f01[KCH], f10[KCH], f11[KCH];
#pragma unroll
    for (int k = 0; k < KCH; k++) {
        int o = k * HW;
        f00[k] = __ldg(feat + a0 + o + x0);
        f01[k] = __ldg(feat + a0 + o + x1);
        f10[k] = __ldg(feat + a1 + o + x0);
        f11[k] = __ldg(feat + a1 + o + x1);
    }

    float omwx = 1.0f - wx;
    float omwy = 1.0f - wy;
    int ob = (n * C_ + c) * NP + i * FS + j;
#pragma unroll
    for (int k = 0; k < KCH; k++) {
        float v = (f00[k] * omwx + f01[k] * wx) * omwy
                + (f10[k] * omwx + f11[k] * wx) * wy;
        // Streaming store: output is write-once; keep L2 for features.
        __stcs(&out[ob + k * NP], v);
    }
}

extern "C" void kernel_launch(void* const* d_in, const int* in_sizes, int n_in,
                              void* d_out, int out_size)
{
    const float* feat = (const float*)d_in[0];
    const float* rois = (const float*)d_in[1];
    float* out = (float*)d_out;

    long tail = (long)out_size - (long)OUT_MAIN_I;
    int tail_blocks = tail > 0 ? (int)((tail + THREADS - 1) / THREADS) : 0;

    pooler_rowwarp_kernel<<<MAIN_BLOCKS + tail_blocks, THREADS>>>(
        feat, rois, out, out_size);
}